// round 7
// baseline (speedup 1.0000x reference)
#include <cuda_runtime.h>
#include <cuda_bf16.h>
#include <cstdint>

// ============================================================================
// TTLinear via dense-W reconstruction + split-precision bf16 HMMA GEMM.
//   W = TT(core0..core3);  out = x @ W^T + bias
//   K=12288 bf16 GEMM: A' = [xhi | xhi | xlo], B' = [Whi | Wlo | Whi]
// GEMM: 128x128 CTA tile, 4 warps, warp tile 64x64 (4 MMA per ldmatrix),
// 3-stage cp.async pipeline, mma.sync m16n8k16 bf16.
// ============================================================================

// ---------------- device scratch (allocation-free rule) ---------------------
__device__ float g_M1[16 * 64 * 64];                  // 256 KB
__device__ float g_M2[16 * 8 * 64 * 8 * 64];          // 16 MB
__device__ __nv_bfloat16 g_Ap[(size_t)2048 * 12288];  // 50 MB
__device__ __nv_bfloat16 g_Bp[(size_t)4096 * 12288];  // 100 MB

// ---------------------------------------------------------------------------
__global__ void compose_m1(const float* __restrict__ core2,
                           const float* __restrict__ core3) {
    int t = blockIdx.x * blockDim.x + threadIdx.x;
    int i23 = t & 63, i2 = i23 >> 3, i3 = i23 & 7;
    int j23 = (t >> 6) & 63, j2 = j23 >> 3, j3 = j23 & 7;
    int a2 = t >> 12;
    float s = 0.f;
#pragma unroll
    for (int a3 = 0; a3 < 16; ++a3)
        s += core2[(a2 * 8 + j2) * 128 + i2 * 16 + a3] * core3[(a3 * 8 + j3) * 8 + i3];
    g_M1[t] = s;
}

__global__ void compose_m2(const float* __restrict__ core1) {
    int t = blockIdx.x * blockDim.x + threadIdx.x;
    int i23 = t & 63;
    int i1 = (t >> 6) & 7;
    int j23 = (t >> 9) & 63;
    int j1 = (t >> 15) & 7;
    int a1 = t >> 18;
    float s = 0.f;
#pragma unroll
    for (int a2 = 0; a2 < 16; ++a2)
        s += core1[(a1 * 8 + j1) * 128 + i1 * 16 + a2] * g_M1[(a2 * 64 + j23) * 64 + i23];
    g_M2[t] = s;
}

__global__ void compose_w(const float* __restrict__ core0) {
    __shared__ float s_c0[1024];
    for (int i = threadIdx.x; i < 1024; i += blockDim.x) s_c0[i] = core0[i];
    __syncthreads();

    int t = blockIdx.x * blockDim.x + threadIdx.x;  // 262144
    int i123 = t & 511, i1 = i123 >> 6, i23 = i123 & 63;
    int j123 = t >> 9, j1 = j123 >> 6, j23 = j123 & 63;

    float m2v[16];
#pragma unroll
    for (int a1 = 0; a1 < 16; ++a1)
        m2v[a1] = g_M2[(((a1 * 8 + j1) * 64 + j23) * 8 + i1) * 64 + i23];

#pragma unroll
    for (int j0 = 0; j0 < 8; ++j0) {
#pragma unroll
        for (int i0 = 0; i0 < 8; ++i0) {
            float s = 0.f;
#pragma unroll
            for (int a1 = 0; a1 < 16; ++a1)
                s += s_c0[j0 * 128 + i0 * 16 + a1] * m2v[a1];
            size_t row = (size_t)(j0 * 512 + j123);
            size_t col = (size_t)(i0 * 512 + i123);
            __nv_bfloat16 hi = __float2bfloat16(s);
            __nv_bfloat16 lo = __float2bfloat16(s - __bfloat162float(hi));
            __nv_bfloat16* b = g_Bp + row * 12288 + col;
            b[0] = hi;
            b[4096] = lo;
            b[8192] = hi;
        }
    }
}

__global__ void convert_x(const float* __restrict__ x) {
    int t = blockIdx.x * blockDim.x + threadIdx.x;  // 2,097,152
    int m = t >> 10;
    int k4 = (t & 1023) * 4;
    float4 v = *(const float4*)(x + (size_t)m * 4096 + k4);
    __nv_bfloat16 h0 = __float2bfloat16(v.x), h1 = __float2bfloat16(v.y);
    __nv_bfloat16 h2 = __float2bfloat16(v.z), h3 = __float2bfloat16(v.w);
    __nv_bfloat16 l0 = __float2bfloat16(v.x - __bfloat162float(h0));
    __nv_bfloat16 l1 = __float2bfloat16(v.y - __bfloat162float(h1));
    __nv_bfloat16 l2 = __float2bfloat16(v.z - __bfloat162float(h2));
    __nv_bfloat16 l3 = __float2bfloat16(v.w - __bfloat162float(h3));
    ushort4 hv = make_ushort4(__bfloat16_as_ushort(h0), __bfloat16_as_ushort(h1),
                              __bfloat16_as_ushort(h2), __bfloat16_as_ushort(h3));
    ushort4 lv = make_ushort4(__bfloat16_as_ushort(l0), __bfloat16_as_ushort(l1),
                              __bfloat16_as_ushort(l2), __bfloat16_as_ushort(l3));
    __nv_bfloat16* a = g_Ap + (size_t)m * 12288 + k4;
    *(ushort4*)(a) = hv;
    *(ushort4*)(a + 4096) = hv;
    *(ushort4*)(a + 8192) = lv;
}

// ---------------------------------------------------------------------------
// HMMA GEMM: C[2048,4096] = A'[2048,12288] @ B'[4096,12288]^T + bias
// ---------------------------------------------------------------------------
#define NKT 192                   // 12288 / 64
#define STAGE_BYTES 32768         // A 16KB + B 16KB
#define SM_TOTAL (3 * STAGE_BYTES)

__device__ __forceinline__ uint32_t smem_u32(const void* p) {
    uint32_t a;
    asm("{ .reg .u64 t; cvta.to.shared.u64 t, %1; cvt.u32.u64 %0, t; }"
        : "=r"(a) : "l"(p));
    return a;
}
__device__ __forceinline__ void cp16(uint32_t dst, const void* src) {
    asm volatile("cp.async.cg.shared.global [%0], [%1], 16;"
                 :: "r"(dst), "l"(src));
}
__device__ __forceinline__ void ldsm4(uint32_t (&r)[4], uint32_t addr) {
    asm volatile("ldmatrix.sync.aligned.m8n8.x4.shared.b16 {%0,%1,%2,%3}, [%4];"
                 : "=r"(r[0]), "=r"(r[1]), "=r"(r[2]), "=r"(r[3]) : "r"(addr));
}
__device__ __forceinline__ void mma16816(float (&d)[4], const uint32_t (&a)[4],
                                         uint32_t b0, uint32_t b1) {
    asm volatile(
        "mma.sync.aligned.m16n8k16.row.col.f32.bf16.bf16.f32 "
        "{%0,%1,%2,%3}, {%4,%5,%6,%7}, {%8,%9}, {%0,%1,%2,%3};"
        : "+f"(d[0]), "+f"(d[1]), "+f"(d[2]), "+f"(d[3])
        : "r"(a[0]), "r"(a[1]), "r"(a[2]), "r"(a[3]), "r"(b0), "r"(b1));
}

__global__ __launch_bounds__(128, 2)
void tt_gemm_mma(const float* __restrict__ bias, float* __restrict__ C) {
    extern __shared__ char smem[];
    const uint32_t sbase = smem_u32(smem);
    const int tid = threadIdx.x;
    const int wid = tid >> 5;
    const int lane = tid & 31;
    const int bm = blockIdx.y * 128;
    const int bn = blockIdx.x * 128;

    const int mw = wid >> 1;     // 0..1 -> m offset 64*mw
    const int nw = wid & 1;      // 0..1 -> n offset 64*nw

    // ---- cp.async producer: each thread owns one A row + one B row (128B/kt) ----
    const int ld_row = tid;                 // 0..127
    const int ld_xor = ld_row & 7;
    const __nv_bfloat16* agp = g_Ap + (size_t)(bm + ld_row) * 12288;
    const __nv_bfloat16* bgp = g_Bp + (size_t)(bn + ld_row) * 12288;
    const uint32_t a_dst_row = sbase + (uint32_t)ld_row * 128;
    const uint32_t b_dst_row = sbase + 16384u + (uint32_t)ld_row * 128;

    auto issue_stage = [&](int kt, int stg) {
        const uint32_t so = (uint32_t)stg * STAGE_BYTES;
        const __nv_bfloat16* asrc = agp + kt * 64;
        const __nv_bfloat16* bsrc = bgp + kt * 64;
#pragma unroll
        for (int q = 0; q < 8; ++q) {
            uint32_t sw = (uint32_t)((q ^ ld_xor) * 16);
            cp16(a_dst_row + so + sw, asrc + q * 8);
            cp16(b_dst_row + so + sw, bsrc + q * 8);
        }
        asm volatile("cp.async.commit_group;" ::: "memory");
    };

    // ---- ldmatrix consumer addresses ----
    const int a_r = mw * 64 + (lane & 15);                          // + mi*16
    const int a_half = lane >> 4;
    const int b_r = nw * 64 + (lane & 7) + ((lane >> 4) & 1) * 8;   // + g*16
    const int b_half = (lane >> 3) & 1;
    const int c_xor = lane & 7;

    float acc[4][8][4];
#pragma unroll
    for (int mi = 0; mi < 4; ++mi)
#pragma unroll
        for (int nf = 0; nf < 8; ++nf)
#pragma unroll
            for (int v = 0; v < 4; ++v) acc[mi][nf][v] = 0.f;

    issue_stage(0, 0);
    issue_stage(1, 1);

    for (int kt = 0; kt < NKT; ++kt) {
        asm volatile("cp.async.wait_group 1;" ::: "memory");
        __syncthreads();
        if (kt + 2 < NKT) issue_stage(kt + 2, (kt + 2) % 3);

        const uint32_t so = (uint32_t)(kt % 3) * STAGE_BYTES;
        const uint32_t abase = sbase + so;
        const uint32_t bbase = sbase + so + 16384u;

#pragma unroll
        for (int s = 0; s < 4; ++s) {
            uint32_t a[4][4];
#pragma unroll
            for (int mi = 0; mi < 4; ++mi) {
                uint32_t ch = (uint32_t)((s * 2 + a_half) ^ c_xor);
                ldsm4(a[mi], abase + (uint32_t)(a_r + mi * 16) * 128 + ch * 16);
            }
            uint32_t b[4][4];
#pragma unroll
            for (int g = 0; g < 4; ++g) {
                uint32_t ch = (uint32_t)((s * 2 + b_half) ^ c_xor);
                ldsm4(b[g], bbase + (uint32_t)(b_r + g * 16) * 128 + ch * 16);
            }
#pragma unroll
            for (int mi = 0; mi < 4; ++mi)
#pragma unroll
                for (int g = 0; g < 4; ++g) {
                    mma16816(acc[mi][2 * g],     a[mi], b[g][0], b[g][1]);
                    mma16816(acc[mi][2 * g + 1], a[mi], b[g][2], b[g][3]);
                }
        }
    }

    // ---- epilogue: + bias, float2 stores ----
    const int er = lane >> 2;            // 0..7
    const int ec = (lane & 3) * 2;       // 0,2,4,6
#pragma unroll
    for (int mi = 0; mi < 4; ++mi) {
        const int m0 = bm + mw * 64 + mi * 16 + er;
#pragma unroll
        for (int nf = 0; nf < 8; ++nf) {
            const int n0 = bn + nw * 64 + nf * 8 + ec;
            const float2 bv = __ldg((const float2*)(bias + n0));
            float2 o0, o1;
            o0.x = acc[mi][nf][0] + bv.x;
            o0.y = acc[mi][nf][1] + bv.y;
            o1.x = acc[mi][nf][2] + bv.x;
            o1.y = acc[mi][nf][3] + bv.y;
            *(float2*)(C + (size_t)m0 * 4096 + n0) = o0;
            *(float2*)(C + (size_t)(m0 + 8) * 4096 + n0) = o1;
        }
    }
}

// ---------------------------------------------------------------------------
extern "C" void kernel_launch(void* const* d_in, const int* in_sizes, int n_in,
                              void* d_out, int out_size) {
    const float* x = (const float*)d_in[0];
    const float* core0 = (const float*)d_in[1];
    const float* core1 = (const float*)d_in[2];
    const float* core2 = (const float*)d_in[3];
    const float* core3 = (const float*)d_in[4];
    const float* bias = (const float*)d_in[5];
    float* out = (float*)d_out;

    cudaFuncSetAttribute(tt_gemm_mma, cudaFuncAttributeMaxDynamicSharedMemorySize, SM_TOTAL);

    convert_x<<<8192, 256>>>(x);
    compose_m1<<<256, 256>>>(core2, core3);
    compose_m2<<<16384, 256>>>(core1);
    compose_w<<<1024, 256>>>(core0);
    dim3 grid(4096 / 128, 2048 / 128);   // 32 x 16 = 512 CTAs
    tt_gemm_mma<<<grid, 128, SM_TOTAL>>>(bias, out);
}

// round 11
// speedup vs baseline: 2.1059x; 2.1059x over previous
#include <cuda_runtime.h>
#include <cuda_fp16.h>
#include <cstdint>

// ============================================================================
// TTLinear via dense-W reconstruction + split-precision fp16 HMMA GEMM.
//   W = TT(core0..core3);  out = x @ W^T + bias
//   fp16 2-term split: x = xhi + xlo (exact to 2^-22);  out ~= [xhi|xlo] @ [Wh|Wh]^T
//   (only dropped term is x*Wlo, rms ~2.8e-4 << 1e-3). B is NOT duplicated:
//   the GEMM loader wraps the B K-index (kt & 63), so working set = 64MB (L2-resident).
// GEMM config = Round-6 (best): 128x128 CTA tile, 8 warps, warp tile 32x64,
// 3-stage cp.async pipeline, mma.sync m16n8k16 fp16, fp32 accumulate.
// ============================================================================

// ---------------- device scratch (allocation-free rule) ---------------------
__device__ float g_M1[16 * 64 * 64];              // 256 KB
__device__ float g_M2[16 * 8 * 64 * 8 * 64];      // 16 MB
__device__ __half g_Ap[(size_t)2048 * 8192];      // 32 MB  [xhi | xlo]
__device__ __half g_Bp[(size_t)4096 * 4096];      // 32 MB  [Whi]

// ---------------------------------------------------------------------------
__global__ void compose_m1(const float* __restrict__ core2,
                           const float* __restrict__ core3) {
    int t = blockIdx.x * blockDim.x + threadIdx.x;
    int i23 = t & 63, i2 = i23 >> 3, i3 = i23 & 7;
    int j23 = (t >> 6) & 63, j2 = j23 >> 3, j3 = j23 & 7;
    int a2 = t >> 12;
    float s = 0.f;
#pragma unroll
    for (int a3 = 0; a3 < 16; ++a3)
        s += core2[(a2 * 8 + j2) * 128 + i2 * 16 + a3] * core3[(a3 * 8 + j3) * 8 + i3];
    g_M1[t] = s;
}

__global__ void compose_m2(const float* __restrict__ core1) {
    int t = blockIdx.x * blockDim.x + threadIdx.x;
    int i23 = t & 63;
    int i1 = (t >> 6) & 7;
    int j23 = (t >> 9) & 63;
    int j1 = (t >> 15) & 7;
    int a1 = t >> 18;
    float s = 0.f;
#pragma unroll
    for (int a2 = 0; a2 < 16; ++a2)
        s += core1[(a1 * 8 + j1) * 128 + i1 * 16 + a2] * g_M1[(a2 * 64 + j23) * 64 + i23];
    g_M2[t] = s;
}

__global__ void compose_w(const float* __restrict__ core0) {
    __shared__ float s_c0[1024];
    for (int i = threadIdx.x; i < 1024; i += blockDim.x) s_c0[i] = core0[i];
    __syncthreads();

    int t = blockIdx.x * blockDim.x + threadIdx.x;  // 262144
    int i123 = t & 511, i1 = i123 >> 6, i23 = i123 & 63;
    int j123 = t >> 9, j1 = j123 >> 6, j23 = j123 & 63;

    float m2v[16];
#pragma unroll
    for (int a1 = 0; a1 < 16; ++a1)
        m2v[a1] = g_M2[(((a1 * 8 + j1) * 64 + j23) * 8 + i1) * 64 + i23];

#pragma unroll
    for (int j0 = 0; j0 < 8; ++j0) {
#pragma unroll
        for (int i0 = 0; i0 < 8; ++i0) {
            float s = 0.f;
#pragma unroll
            for (int a1 = 0; a1 < 16; ++a1)
                s += s_c0[j0 * 128 + i0 * 16 + a1] * m2v[a1];
            size_t row = (size_t)(j0 * 512 + j123);
            size_t col = (size_t)(i0 * 512 + i123);
            g_Bp[row * 4096 + col] = __float2half(s);
        }
    }
}

// Convert x -> A' = [xhi | xlo] fp16; 4 elements per thread.
// NEEDS 2048 rows x 1024 quads = 2,097,152 threads (grid 8192 x 256).
__global__ void convert_x(const float* __restrict__ x) {
    int t = blockIdx.x * blockDim.x + threadIdx.x;
    int m = t >> 10;
    int k4 = (t & 1023) * 4;
    float4 v = *(const float4*)(x + (size_t)m * 4096 + k4);
    __half h0 = __float2half(v.x), h1 = __float2half(v.y);
    __half h2 = __float2half(v.z), h3 = __float2half(v.w);
    __half l0 = __float2half(v.x - __half2float(h0));
    __half l1 = __float2half(v.y - __half2float(h1));
    __half l2 = __float2half(v.z - __half2float(h2));
    __half l3 = __float2half(v.w - __half2float(h3));
    ushort4 hv = make_ushort4(__half_as_ushort(h0), __half_as_ushort(h1),
                              __half_as_ushort(h2), __half_as_ushort(h3));
    ushort4 lv = make_ushort4(__half_as_ushort(l0), __half_as_ushort(l1),
                              __half_as_ushort(l2), __half_as_ushort(l3));
    __half* a = g_Ap + (size_t)m * 8192 + k4;
    *(ushort4*)(a) = hv;
    *(ushort4*)(a + 4096) = lv;
}

// ---------------------------------------------------------------------------
// HMMA GEMM: C[2048,4096] = A'[2048,8192] @ B[4096,4096(wrapped)]^T + bias
// ---------------------------------------------------------------------------
#define NKT 128                   // 8192 / 64
#define STAGE_BYTES 32768         // A 16KB + B 16KB
#define SM_TOTAL (3 * STAGE_BYTES)

__device__ __forceinline__ uint32_t smem_u32(const void* p) {
    uint32_t a;
    asm("{ .reg .u64 t; cvta.to.shared.u64 t, %1; cvt.u32.u64 %0, t; }"
        : "=r"(a) : "l"(p));
    return a;
}
__device__ __forceinline__ void cp16(uint32_t dst, const void* src) {
    asm volatile("cp.async.cg.shared.global [%0], [%1], 16;"
                 :: "r"(dst), "l"(src));
}
__device__ __forceinline__ void ldsm4(uint32_t (&r)[4], uint32_t addr) {
    asm volatile("ldmatrix.sync.aligned.m8n8.x4.shared.b16 {%0,%1,%2,%3}, [%4];"
                 : "=r"(r[0]), "=r"(r[1]), "=r"(r[2]), "=r"(r[3]) : "r"(addr));
}
__device__ __forceinline__ void mma16816(float (&d)[4], const uint32_t (&a)[4],
                                         uint32_t b0, uint32_t b1) {
    asm volatile(
        "mma.sync.aligned.m16n8k16.row.col.f32.f16.f16.f32 "
        "{%0,%1,%2,%3}, {%4,%5,%6,%7}, {%8,%9}, {%0,%1,%2,%3};"
        : "+f"(d[0]), "+f"(d[1]), "+f"(d[2]), "+f"(d[3])
        : "r"(a[0]), "r"(a[1]), "r"(a[2]), "r"(a[3]), "r"(b0), "r"(b1));
}

__global__ __launch_bounds__(256, 2)
void tt_gemm_mma(const float* __restrict__ bias, float* __restrict__ C) {
    extern __shared__ char smem[];
    const uint32_t sbase = smem_u32(smem);
    const int tid = threadIdx.x;
    const int wid = tid >> 5;
    const int lane = tid & 31;
    const int bm = blockIdx.y * 128;
    const int bn = blockIdx.x * 128;

    const int mw = wid >> 1;     // 0..3 -> m offset 32*mw
    const int nw = wid & 1;      // 0..1 -> n offset 64*nw

    // ---- cp.async producer: 128 rows x 8 chunks(16B) per operand ----
    const int ld_row = tid >> 1;           // 0..127
    const int ld_seg = (tid & 1) * 4;      // chunk 0..3 or 4..7
    const int ld_xor = ld_row & 7;
    const __half* agp = g_Ap + (size_t)(bm + ld_row) * 8192 + ld_seg * 8;
    const __half* bgp = g_Bp + (size_t)(bn + ld_row) * 4096 + ld_seg * 8;
    const uint32_t a_dst_row = sbase + (uint32_t)ld_row * 128;
    const uint32_t b_dst_row = sbase + 16384u + (uint32_t)ld_row * 128;

    auto issue_stage = [&](int kt, int stg) {
        const uint32_t so = (uint32_t)stg * STAGE_BYTES;
        const __half* asrc = agp + kt * 64;
        const __half* bsrc = bgp + (kt & 63) * 64;   // B wraps: [Wh|Wh] virtually
#pragma unroll
        for (int q = 0; q < 4; ++q) {
            uint32_t sw = (uint32_t)(((ld_seg + q) ^ ld_xor) * 16);
            cp16(a_dst_row + so + sw, asrc + q * 8);
            cp16(b_dst_row + so + sw, bsrc + q * 8);
        }
        asm volatile("cp.async.commit_group;" ::: "memory");
    };

    // ---- ldmatrix consumer addresses ----
    const int a_r = mw * 32 + (lane & 15);                          // + mi*16
    const int a_half = lane >> 4;
    const int b_r = nw * 64 + (lane & 7) + ((lane >> 4) & 1) * 8;   // + g*16
    const int b_half = (lane >> 3) & 1;
    const int c_xor = lane & 7;

    float acc[2][8][4];
#pragma unroll
    for (int mi = 0; mi < 2; ++mi)
#pragma unroll
        for (int nf = 0; nf < 8; ++nf)
#pragma unroll
            for (int v = 0; v < 4; ++v) acc[mi][nf][v] = 0.f;

    issue_stage(0, 0);
    issue_stage(1, 1);

    for (int kt = 0; kt < NKT; ++kt) {
        asm volatile("cp.async.wait_group 1;" ::: "memory");
        __syncthreads();
        if (kt + 2 < NKT) issue_stage(kt + 2, (kt + 2) % 3);

        const uint32_t so = (uint32_t)(kt % 3) * STAGE_BYTES;
        const uint32_t abase = sbase + so;
        const uint32_t bbase = sbase + so + 16384u;

#pragma unroll
        for (int s = 0; s < 4; ++s) {
            uint32_t a[2][4];
#pragma unroll
            for (int mi = 0; mi < 2; ++mi) {
                uint32_t ch = (uint32_t)((s * 2 + a_half) ^ c_xor);
                ldsm4(a[mi], abase + (uint32_t)(a_r + mi * 16) * 128 + ch * 16);
            }
            uint32_t b[4][4];
#pragma unroll
            for (int g = 0; g < 4; ++g) {
                uint32_t ch = (uint32_t)((s * 2 + b_half) ^ c_xor);
                ldsm4(b[g], bbase + (uint32_t)(b_r + g * 16) * 128 + ch * 16);
            }
#pragma unroll
            for (int mi = 0; mi < 2; ++mi)
#pragma unroll
                for (int g = 0; g < 4; ++g) {
                    mma16816(acc[mi][2 * g],     a[mi], b[g][0], b[g][1]);
                    mma16816(acc[mi][2 * g + 1], a[mi], b[g][2], b[g][3]);
                }
        }
    }

    // ---- epilogue: + bias, float2 stores ----
    const int er = lane >> 2;            // 0..7
    const int ec = (lane & 3) * 2;       // 0,2,4,6
#pragma unroll
    for (int mi = 0; mi < 2; ++mi) {
        const int m0 = bm + mw * 32 + mi * 16 + er;
#pragma unroll
        for (int nf = 0; nf < 8; ++nf) {
            const int n0 = bn + nw * 64 + nf * 8 + ec;
            const float2 bv = __ldg((const float2*)(bias + n0));
            float2 o0, o1;
            o0.x = acc[mi][nf][0] + bv.x;
            o0.y = acc[mi][nf][1] + bv.y;
            o1.x = acc[mi][nf][2] + bv.x;
            o1.y = acc[mi][nf][3] + bv.y;
            *(float2*)(C + (size_t)m0 * 4096 + n0) = o0;
            *(float2*)(C + (size_t)(m0 + 8) * 4096 + n0) = o1;
        }
    }
}

// ---------------------------------------------------------------------------
extern "C" void kernel_launch(void* const* d_in, const int* in_sizes, int n_in,
                              void* d_out, int out_size) {
    const float* x = (const float*)d_in[0];
    const float* core0 = (const float*)d_in[1];
    const float* core1 = (const float*)d_in[2];
    const float* core2 = (const float*)d_in[3];
    const float* core3 = (const float*)d_in[4];
    const float* bias = (const float*)d_in[5];
    float* out = (float*)d_out;

    cudaFuncSetAttribute(tt_gemm_mma, cudaFuncAttributeMaxDynamicSharedMemorySize, SM_TOTAL);

    convert_x<<<8192, 256>>>(x);     // FIX: full batch (was 2048 -> only 512 rows)
    compose_m1<<<256, 256>>>(core2, core3);
    compose_m2<<<16384, 256>>>(core1);
    compose_w<<<1024, 256>>>(core0);
    dim3 grid(4096 / 128, 2048 / 128);   // 32 x 16 = 512 CTAs
    tt_gemm_mma<<<grid, 256, SM_TOTAL>>>(bias, out);
}

// round 14
// speedup vs baseline: 3.7143x; 1.7638x over previous
#include <cuda_runtime.h>
#include <cuda_fp16.h>
#include <cstdint>

// ============================================================================
// TTLinear via dense-W reconstruction + fp16 HMMA GEMM (single-term).
//   W = TT(core0..core3);  out = x @ W^T + bias
//   out ~= fp16(x) @ fp16(W)^T, fp32 accumulate.
//   Calibrated error model (R11): one fp16-rounded operand -> 2.08e-4 rel_err.
//   Two rounded operands -> sqrt(2)*2.08e-4 ~ 2.9e-4  (<< 1e-3 threshold).
// GEMM config = Round-6 (best): 128x128 CTA tile, 8 warps, warp tile 32x64,
// 3-stage cp.async pipeline, mma.sync m16n8k16 fp16, K=4096 (NKT=64).
// Working set: A 16MB + B 32MB = 48MB, fully L2-resident.
// ============================================================================

// ---------------- device scratch (allocation-free rule) ---------------------
__device__ float g_M1[16 * 64 * 64];              // 256 KB
__device__ float g_M2[16 * 8 * 64 * 8 * 64];      // 16 MB
__device__ __half g_Ap[(size_t)2048 * 4096];      // 16 MB  fp16(x)
__device__ __half g_Bp[(size_t)4096 * 4096];      // 32 MB  fp16(W)

// ---------------------------------------------------------------------------
__global__ void compose_m1(const float* __restrict__ core2,
                           const float* __restrict__ core3) {
    int t = blockIdx.x * blockDim.x + threadIdx.x;
    int i23 = t & 63, i2 = i23 >> 3, i3 = i23 & 7;
    int j23 = (t >> 6) & 63, j2 = j23 >> 3, j3 = j23 & 7;
    int a2 = t >> 12;
    float s = 0.f;
#pragma unroll
    for (int a3 = 0; a3 < 16; ++a3)
        s += core2[(a2 * 8 + j2) * 128 + i2 * 16 + a3] * core3[(a3 * 8 + j3) * 8 + i3];
    g_M1[t] = s;
}

__global__ void compose_m2(const float* __restrict__ core1) {
    int t = blockIdx.x * blockDim.x + threadIdx.x;
    int i23 = t & 63;
    int i1 = (t >> 6) & 7;
    int j23 = (t >> 9) & 63;
    int j1 = (t >> 15) & 7;
    int a1 = t >> 18;
    float s = 0.f;
#pragma unroll
    for (int a2 = 0; a2 < 16; ++a2)
        s += core1[(a1 * 8 + j1) * 128 + i1 * 16 + a2] * g_M1[(a2 * 64 + j23) * 64 + i23];
    g_M2[t] = s;
}

__global__ void compose_w(const float* __restrict__ core0) {
    __shared__ float s_c0[1024];
    for (int i = threadIdx.x; i < 1024; i += blockDim.x) s_c0[i] = core0[i];
    __syncthreads();

    int t = blockIdx.x * blockDim.x + threadIdx.x;  // 262144
    int i123 = t & 511, i1 = i123 >> 6, i23 = i123 & 63;
    int j123 = t >> 9, j1 = j123 >> 6, j23 = j123 & 63;

    float m2v[16];
#pragma unroll
    for (int a1 = 0; a1 < 16; ++a1)
        m2v[a1] = g_M2[(((a1 * 8 + j1) * 64 + j23) * 8 + i1) * 64 + i23];

#pragma unroll
    for (int j0 = 0; j0 < 8; ++j0) {
#pragma unroll
        for (int i0 = 0; i0 < 8; ++i0) {
            float s = 0.f;
#pragma unroll
            for (int a1 = 0; a1 < 16; ++a1)
                s += s_c0[j0 * 128 + i0 * 16 + a1] * m2v[a1];
            size_t row = (size_t)(j0 * 512 + j123);
            size_t col = (size_t)(i0 * 512 + i123);
            g_Bp[row * 4096 + col] = __float2half(s);
        }
    }
}

// Convert x -> fp16; 4 elements per thread. 2048x1024 quads -> grid 8192x256.
__global__ void convert_x(const float* __restrict__ x) {
    int t = blockIdx.x * blockDim.x + threadIdx.x;
    int m = t >> 10;
    int k4 = (t & 1023) * 4;
    float4 v = *(const float4*)(x + (size_t)m * 4096 + k4);
    ushort4 hv = make_ushort4(__half_as_ushort(__float2half(v.x)),
                              __half_as_ushort(__float2half(v.y)),
                              __half_as_ushort(__float2half(v.z)),
                              __half_as_ushort(__float2half(v.w)));
    *(ushort4*)(g_Ap + (size_t)m * 4096 + k4) = hv;
}

// ---------------------------------------------------------------------------
// HMMA GEMM: C[2048,4096] = A[2048,4096] @ B[4096,4096]^T + bias
// ---------------------------------------------------------------------------
#define NKT 64                    // 4096 / 64
#define STAGE_BYTES 32768         // A 16KB + B 16KB
#define SM_TOTAL (3 * STAGE_BYTES)

__device__ __forceinline__ uint32_t smem_u32(const void* p) {
    uint32_t a;
    asm("{ .reg .u64 t; cvta.to.shared.u64 t, %1; cvt.u32.u64 %0, t; }"
        : "=r"(a) : "l"(p));
    return a;
}
__device__ __forceinline__ void cp16(uint32_t dst, const void* src) {
    asm volatile("cp.async.cg.shared.global [%0], [%1], 16;"
                 :: "r"(dst), "l"(src));
}
__device__ __forceinline__ void ldsm4(uint32_t (&r)[4], uint32_t addr) {
    asm volatile("ldmatrix.sync.aligned.m8n8.x4.shared.b16 {%0,%1,%2,%3}, [%4];"
                 : "=r"(r[0]), "=r"(r[1]), "=r"(r[2]), "=r"(r[3]) : "r"(addr));
}
__device__ __forceinline__ void mma16816(float (&d)[4], const uint32_t (&a)[4],
                                         uint32_t b0, uint32_t b1) {
    asm volatile(
        "mma.sync.aligned.m16n8k16.row.col.f32.f16.f16.f32 "
        "{%0,%1,%2,%3}, {%4,%5,%6,%7}, {%8,%9}, {%0,%1,%2,%3};"
        : "+f"(d[0]), "+f"(d[1]), "+f"(d[2]), "+f"(d[3])
        : "r"(a[0]), "r"(a[1]), "r"(a[2]), "r"(a[3]), "r"(b0), "r"(b1));
}

__global__ __launch_bounds__(256, 2)
void tt_gemm_mma(const float* __restrict__ bias, float* __restrict__ C) {
    extern __shared__ char smem[];
    const uint32_t sbase = smem_u32(smem);
    const int tid = threadIdx.x;
    const int wid = tid >> 5;
    const int lane = tid & 31;
    const int bm = blockIdx.y * 128;
    const int bn = blockIdx.x * 128;

    const int mw = wid >> 1;     // 0..3 -> m offset 32*mw
    const int nw = wid & 1;      // 0..1 -> n offset 64*nw

    // ---- cp.async producer: 128 rows x 8 chunks(16B) per operand ----
    const int ld_row = tid >> 1;           // 0..127
    const int ld_seg = (tid & 1) * 4;      // chunk 0..3 or 4..7
    const int ld_xor = ld_row & 7;
    const __half* agp = g_Ap + (size_t)(bm + ld_row) * 4096 + ld_seg * 8;
    const __half* bgp = g_Bp + (size_t)(bn + ld_row) * 4096 + ld_seg * 8;
    const uint32_t a_dst_row = sbase + (uint32_t)ld_row * 128;
    const uint32_t b_dst_row = sbase + 16384u + (uint32_t)ld_row * 128;

    auto issue_stage = [&](int kt, int stg) {
        const uint32_t so = (uint32_t)stg * STAGE_BYTES;
        const __half* asrc = agp + kt * 64;
        const __half* bsrc = bgp + kt * 64;
#pragma unroll
        for (int q = 0; q < 4; ++q) {
            uint32_t sw = (uint32_t)(((ld_seg + q) ^ ld_xor) * 16);
            cp16(a_dst_row + so + sw, asrc + q * 8);
            cp16(b_dst_row + so + sw, bsrc + q * 8);
        }
        asm volatile("cp.async.commit_group;" ::: "memory");
    };

    // ---- ldmatrix consumer addresses ----
    const int a_r = mw * 32 + (lane & 15);                          // + mi*16
    const int a_half = lane >> 4;
    const int b_r = nw * 64 + (lane & 7) + ((lane >> 4) & 1) * 8;   // + g*16
    const int b_half = (lane >> 3) & 1;
    const int c_xor = lane & 7;

    float acc[2][8][4];
#pragma unroll
    for (int mi = 0; mi < 2; ++mi)
#pragma unroll
        for (int nf = 0; nf < 8; ++nf)
#pragma unroll
            for (int v = 0; v < 4; ++v) acc[mi][nf][v] = 0.f;

    issue_stage(0, 0);
    issue_stage(1, 1);

    for (int kt = 0; kt < NKT; ++kt) {
        asm volatile("cp.async.wait_group 1;" ::: "memory");
        __syncthreads();
        if (kt + 2 < NKT) issue_stage(kt + 2, (kt + 2) % 3);

        const uint32_t so = (uint32_t)(kt % 3) * STAGE_BYTES;
        const uint32_t abase = sbase + so;
        const uint32_t bbase = sbase + so + 16384u;

#pragma unroll
        for (int s = 0; s < 4; ++s) {
            uint32_t a[2][4];
#pragma unroll
            for (int mi = 0; mi < 2; ++mi) {
                uint32_t ch = (uint32_t)((s * 2 + a_half) ^ c_xor);
                ldsm4(a[mi], abase + (uint32_t)(a_r + mi * 16) * 128 + ch * 16);
            }
            uint32_t b[4][4];
#pragma unroll
            for (int g = 0; g < 4; ++g) {
                uint32_t ch = (uint32_t)((s * 2 + b_half) ^ c_xor);
                ldsm4(b[g], bbase + (uint32_t)(b_r + g * 16) * 128 + ch * 16);
            }
#pragma unroll
            for (int mi = 0; mi < 2; ++mi)
#pragma unroll
                for (int g = 0; g < 4; ++g) {
                    mma16816(acc[mi][2 * g],     a[mi], b[g][0], b[g][1]);
                    mma16816(acc[mi][2 * g + 1], a[mi], b[g][2], b[g][3]);
                }
        }
    }

    // ---- epilogue: + bias, float2 stores ----
    const int er = lane >> 2;            // 0..7
    const int ec = (lane & 3) * 2;       // 0,2,4,6
#pragma unroll
    for (int mi = 0; mi < 2; ++mi) {
        const int m0 = bm + mw * 32 + mi * 16 + er;
#pragma unroll
        for (int nf = 0; nf < 8; ++nf) {
            const int n0 = bn + nw * 64 + nf * 8 + ec;
            const float2 bv = __ldg((const float2*)(bias + n0));
            float2 o0, o1;
            o0.x = acc[mi][nf][0] + bv.x;
            o0.y = acc[mi][nf][1] + bv.y;
            o1.x = acc[mi][nf][2] + bv.x;
            o1.y = acc[mi][nf][3] + bv.y;
            *(float2*)(C + (size_t)m0 * 4096 + n0) = o0;
            *(float2*)(C + (size_t)(m0 + 8) * 4096 + n0) = o1;
        }
    }
}

// ---------------------------------------------------------------------------
extern "C" void kernel_launch(void* const* d_in, const int* in_sizes, int n_in,
                              void* d_out, int out_size) {
    const float* x = (const float*)d_in[0];
    const float* core0 = (const float*)d_in[1];
    const float* core1 = (const float*)d_in[2];
    const float* core2 = (const float*)d_in[3];
    const float* core3 = (const float*)d_in[4];
    const float* bias = (const float*)d_in[5];
    float* out = (float*)d_out;

    cudaFuncSetAttribute(tt_gemm_mma, cudaFuncAttributeMaxDynamicSharedMemorySize, SM_TOTAL);

    convert_x<<<8192, 256>>>(x);
    compose_m1<<<256, 256>>>(core2, core3);
    compose_m2<<<16384, 256>>>(core1);
    compose_w<<<1024, 256>>>(core0);
    dim3 grid(4096 / 128, 2048 / 128);   // 32 x 16 = 512 CTAs
    tt_gemm_mma<<<grid, 256, SM_TOTAL>>>(bias, out);
}

// round 16
// speedup vs baseline: 3.8512x; 1.0369x over previous
#include <cuda_runtime.h>
#include <cuda_fp16.h>
#include <cstdint>

// ============================================================================
// TTLinear via dense-W reconstruction + fp16 HMMA GEMM (single-term).
//   W = TT(core0..core3);  out = x @ W^T + bias
//   out ~= fp16(x) @ fp16(W)^T, fp32 accumulate. rel_err ~2.9e-4 (calibrated).
// This round: compose_m2 + compose_w fused (no 16MB M2 round-trip).
// GEMM config = Round-6 (best, at MMA-pipe floor): 128x128 CTA tile, 8 warps,
// warp tile 32x64, 3-stage cp.async, mma.sync m16n8k16 fp16, K=4096.
// ============================================================================

// ---------------- device scratch (allocation-free rule) ---------------------
__device__ float g_M1[16 * 64 * 64];              // 256 KB
__device__ __half g_Ap[(size_t)2048 * 4096];      // 16 MB  fp16(x)
__device__ __half g_Bp[(size_t)4096 * 4096];      // 32 MB  fp16(W)

// ---------------------------------------------------------------------------
// Step 1: M1[a2, j2 j3, i2 i3] = sum_a3 core2[a2*8+j2, i2*16+a3] * core3[a3*8+j3, i3]
__global__ void compose_m1(const float* __restrict__ core2,
                           const float* __restrict__ core3) {
    int t = blockIdx.x * blockDim.x + threadIdx.x;
    int i23 = t & 63, i2 = i23 >> 3, i3 = i23 & 7;
    int j23 = (t >> 6) & 63, j2 = j23 >> 3, j3 = j23 & 7;
    int a2 = t >> 12;
    float s = 0.f;
#pragma unroll
    for (int a3 = 0; a3 < 16; ++a3)
        s += core2[(a2 * 8 + j2) * 128 + i2 * 16 + a3] * core3[(a3 * 8 + j3) * 8 + i3];
    g_M1[t] = s;
}

// ---------------------------------------------------------------------------
// Fused steps 2+3:
//   m2v[a1] = sum_a2 core1[(a1*8+j1), i1*16+a2] * M1[a2, j23, i23]   (on the fly)
//   W[(j0*512+j123), (i0*512+i123)] = sum_a1 core0[j0, i0*16+a1] * m2v[a1]
// Block: 256 threads; blockIdx encodes (j123, half-of-i123) -> j1, j23 const.
__global__ void compose_m2w(const float* __restrict__ core0,
                            const float* __restrict__ core1) {
    __shared__ float s_c0[1024];      // core0: 8 x 128
    __shared__ float s_c1[16 * 128];  // core1 rows (a1*8 + j1), a1 = 0..15
    __shared__ float s_m1[16 * 64];   // M1[a2, j23, :]

    const int j123 = blockIdx.x >> 1;                       // 0..511
    const int i123 = (blockIdx.x & 1) * 256 + threadIdx.x;  // 0..511
    const int j1 = j123 >> 6, j23 = j123 & 63;
    const int i1 = i123 >> 6, i23 = i123 & 63;

    for (int idx = threadIdx.x; idx < 1024; idx += 256)
        s_c0[idx] = core0[idx];
    for (int idx = threadIdx.x; idx < 2048; idx += 256) {
        int a1 = idx >> 7, col = idx & 127;
        s_c1[idx] = core1[(a1 * 8 + j1) * 128 + col];
    }
    for (int idx = threadIdx.x; idx < 1024; idx += 256) {
        int a2 = idx >> 6, ii = idx & 63;
        s_m1[idx] = g_M1[(a2 * 64 + j23) * 64 + ii];
    }
    __syncthreads();

    float m2v[16];
#pragma unroll
    for (int a1 = 0; a1 < 16; ++a1) {
        float s = 0.f;
#pragma unroll
        for (int a2 = 0; a2 < 16; ++a2)
            s += s_c1[a1 * 128 + i1 * 16 + a2] * s_m1[a2 * 64 + i23];
        m2v[a1] = s;
    }

#pragma unroll
    for (int j0 = 0; j0 < 8; ++j0) {
#pragma unroll
        for (int i0 = 0; i0 < 8; ++i0) {
            float s = 0.f;
#pragma unroll
            for (int a1 = 0; a1 < 16; ++a1)
                s += s_c0[j0 * 128 + i0 * 16 + a1] * m2v[a1];
            size_t row = (size_t)(j0 * 512 + j123);
            size_t col = (size_t)(i0 * 512 + i123);
            g_Bp[row * 4096 + col] = __float2half(s);
        }
    }
}

// Convert x -> fp16; 4 elements per thread. 2048x1024 quads -> grid 8192x256.
__global__ void convert_x(const float* __restrict__ x) {
    int t = blockIdx.x * blockDim.x + threadIdx.x;
    int m = t >> 10;
    int k4 = (t & 1023) * 4;
    float4 v = *(const float4*)(x + (size_t)m * 4096 + k4);
    ushort4 hv = make_ushort4(__half_as_ushort(__float2half(v.x)),
                              __half_as_ushort(__float2half(v.y)),
                              __half_as_ushort(__float2half(v.z)),
                              __half_as_ushort(__float2half(v.w)));
    *(ushort4*)(g_Ap + (size_t)m * 4096 + k4) = hv;
}

// ---------------------------------------------------------------------------
// HMMA GEMM: C[2048,4096] = A[2048,4096] @ B[4096,4096]^T + bias
// ---------------------------------------------------------------------------
#define NKT 64                    // 4096 / 64
#define STAGE_BYTES 32768         // A 16KB + B 16KB
#define SM_TOTAL (3 * STAGE_BYTES)

__device__ __forceinline__ uint32_t smem_u32(const void* p) {
    uint32_t a;
    asm("{ .reg .u64 t; cvta.to.shared.u64 t, %1; cvt.u32.u64 %0, t; }"
        : "=r"(a) : "l"(p));
    return a;
}
__device__ __forceinline__ void cp16(uint32_t dst, const void* src) {
    asm volatile("cp.async.cg.shared.global [%0], [%1], 16;"
                 :: "r"(dst), "l"(src));
}
__device__ __forceinline__ void ldsm4(uint32_t (&r)[4], uint32_t addr) {
    asm volatile("ldmatrix.sync.aligned.m8n8.x4.shared.b16 {%0,%1,%2,%3}, [%4];"
                 : "=r"(r[0]), "=r"(r[1]), "=r"(r[2]), "=r"(r[3]) : "r"(addr));
}
__device__ __forceinline__ void mma16816(float (&d)[4], const uint32_t (&a)[4],
                                         uint32_t b0, uint32_t b1) {
    asm volatile(
        "mma.sync.aligned.m16n8k16.row.col.f32.f16.f16.f32 "
        "{%0,%1,%2,%3}, {%4,%5,%6,%7}, {%8,%9}, {%0,%1,%2,%3};"
        : "+f"(d[0]), "+f"(d[1]), "+f"(d[2]), "+f"(d[3])
        : "r"(a[0]), "r"(a[1]), "r"(a[2]), "r"(a[3]), "r"(b0), "r"(b1));
}

__global__ __launch_bounds__(256, 2)
void tt_gemm_mma(const float* __restrict__ bias, float* __restrict__ C) {
    extern __shared__ char smem[];
    const uint32_t sbase = smem_u32(smem);
    const int tid = threadIdx.x;
    const int wid = tid >> 5;
    const int lane = tid & 31;
    const int bm = blockIdx.y * 128;
    const int bn = blockIdx.x * 128;

    const int mw = wid >> 1;     // 0..3 -> m offset 32*mw
    const int nw = wid & 1;      // 0..1 -> n offset 64*nw

    // ---- cp.async producer: 128 rows x 8 chunks(16B) per operand ----
    const int ld_row = tid >> 1;           // 0..127
    const int ld_seg = (tid & 1) * 4;      // chunk 0..3 or 4..7
    const int ld_xor = ld_row & 7;
    const __half* agp = g_Ap + (size_t)(bm + ld_row) * 4096 + ld_seg * 8;
    const __half* bgp = g_Bp + (size_t)(bn + ld_row) * 4096 + ld_seg * 8;
    const uint32_t a_dst_row = sbase + (uint32_t)ld_row * 128;
    const uint32_t b_dst_row = sbase + 16384u + (uint32_t)ld_row * 128;

    auto issue_stage = [&](int kt, int stg) {
        const uint32_t so = (uint32_t)stg * STAGE_BYTES;
        const __half* asrc = agp + kt * 64;
        const __half* bsrc = bgp + kt * 64;
#pragma unroll
        for (int q = 0; q < 4; ++q) {
            uint32_t sw = (uint32_t)(((ld_seg + q) ^ ld_xor) * 16);
            cp16(a_dst_row + so + sw, asrc + q * 8);
            cp16(b_dst_row + so + sw, bsrc + q * 8);
        }
        asm volatile("cp.async.commit_group;" ::: "memory");
    };

    // ---- ldmatrix consumer addresses ----
    const int a_r = mw * 32 + (lane & 15);                          // + mi*16
    const int a_half = lane >> 4;
    const int b_r = nw * 64 + (lane & 7) + ((lane >> 4) & 1) * 8;   // + g*16
    const int b_half = (lane >> 3) & 1;
    const int c_xor = lane & 7;

    float acc[2][8][4];
#pragma unroll
    for (int mi = 0; mi < 2; ++mi)
#pragma unroll
        for (int nf = 0; nf < 8; ++nf)
#pragma unroll
            for (int v = 0; v < 4; ++v) acc[mi][nf][v] = 0.f;

    issue_stage(0, 0);
    issue_stage(1, 1);

    for (int kt = 0; kt < NKT; ++kt) {
        asm volatile("cp.async.wait_group 1;" ::: "memory");
        __syncthreads();
        if (kt + 2 < NKT) issue_stage(kt + 2, (kt + 2) % 3);

        const uint32_t so = (uint32_t)(kt % 3) * STAGE_BYTES;
        const uint32_t abase = sbase + so;
        const uint32_t bbase = sbase + so + 16384u;

#pragma unroll
        for (int s = 0; s < 4; ++s) {
            uint32_t a[2][4];
#pragma unroll
            for (int mi = 0; mi < 2; ++mi) {
                uint32_t ch = (uint32_t)((s * 2 + a_half) ^ c_xor);
                ldsm4(a[mi], abase + (uint32_t)(a_r + mi * 16) * 128 + ch * 16);
            }
            uint32_t b[4][4];
#pragma unroll
            for (int g = 0; g < 4; ++g) {
                uint32_t ch = (uint32_t)((s * 2 + b_half) ^ c_xor);
                ldsm4(b[g], bbase + (uint32_t)(b_r + g * 16) * 128 + ch * 16);
            }
#pragma unroll
            for (int mi = 0; mi < 2; ++mi)
#pragma unroll
                for (int g = 0; g < 4; ++g) {
                    mma16816(acc[mi][2 * g],     a[mi], b[g][0], b[g][1]);
                    mma16816(acc[mi][2 * g + 1], a[mi], b[g][2], b[g][3]);
                }
        }
    }

    // ---- epilogue: + bias, float2 stores ----
    const int er = lane >> 2;            // 0..7
    const int ec = (lane & 3) * 2;       // 0,2,4,6
#pragma unroll
    for (int mi = 0; mi < 2; ++mi) {
        const int m0 = bm + mw * 32 + mi * 16 + er;
#pragma unroll
        for (int nf = 0; nf < 8; ++nf) {
            const int n0 = bn + nw * 64 + nf * 8 + ec;
            const float2 bv = __ldg((const float2*)(bias + n0));
            float2 o0, o1;
            o0.x = acc[mi][nf][0] + bv.x;
            o0.y = acc[mi][nf][1] + bv.y;
            o1.x = acc[mi][nf][2] + bv.x;
            o1.y = acc[mi][nf][3] + bv.y;
            *(float2*)(C + (size_t)m0 * 4096 + n0) = o0;
            *(float2*)(C + (size_t)(m0 + 8) * 4096 + n0) = o1;
        }
    }
}

// ---------------------------------------------------------------------------
extern "C" void kernel_launch(void* const* d_in, const int* in_sizes, int n_in,
                              void* d_out, int out_size) {
    const float* x = (const float*)d_in[0];
    const float* core0 = (const float*)d_in[1];
    const float* core1 = (const float*)d_in[2];
    const float* core2 = (const float*)d_in[3];
    const float* core3 = (const float*)d_in[4];
    const float* bias = (const float*)d_in[5];
    float* out = (float*)d_out;

    cudaFuncSetAttribute(tt_gemm_mma, cudaFuncAttributeMaxDynamicSharedMemorySize, SM_TOTAL);

    convert_x<<<8192, 256>>>(x);
    compose_m1<<<256, 256>>>(core2, core3);
    compose_m2w<<<1024, 256>>>(core0, core1);
    dim3 grid(4096 / 128, 2048 / 128);   // 32 x 16 = 512 CTAs
    tt_gemm_mma<<<grid, 256, SM_TOTAL>>>(bias, out);
}

// round 17
// speedup vs baseline: 3.9588x; 1.0279x over previous
#include <cuda_runtime.h>
#include <cuda_fp16.h>
#include <cstdint>

// ============================================================================
// TTLinear via dense-W reconstruction + fp16 HMMA GEMM (single-term).
//   out ~= fp16(x) @ fp16(W)^T + bias, fp32 accumulate. rel_err 2.94e-4 (calibrated).
// GEMM is at the legacy-HMMA issue floor (rt_SMSP=16, two-point verified);
// this round optimizes the aux chain: 4-wide fused compose, stitched convert+m1.
// ============================================================================

// ---------------- device scratch (allocation-free rule) ---------------------
__device__ float g_M1[16 * 64 * 64];              // 256 KB
__device__ __half g_Ap[(size_t)2048 * 4096];      // 16 MB  fp16(x)
__device__ __half g_Bp[(size_t)4096 * 4096];      // 32 MB  fp16(W)

// ---------------------------------------------------------------------------
// Stitched: blocks [0,8192) convert x -> fp16; blocks [8192,8448) build M1.
//   M1[a2, j2 j3, i2 i3] = sum_a3 core2[a2*8+j2, i2*16+a3] * core3[a3*8+j3, i3]
__global__ void convert_and_m1(const float* __restrict__ x,
                               const float* __restrict__ core2,
                               const float* __restrict__ core3) {
    if (blockIdx.x < 8192) {
        int t = blockIdx.x * 256 + threadIdx.x;
        int m = t >> 10;
        int k4 = (t & 1023) * 4;
        float4 v = *(const float4*)(x + (size_t)m * 4096 + k4);
        ushort4 hv = make_ushort4(__half_as_ushort(__float2half(v.x)),
                                  __half_as_ushort(__float2half(v.y)),
                                  __half_as_ushort(__float2half(v.z)),
                                  __half_as_ushort(__float2half(v.w)));
        *(ushort4*)(g_Ap + (size_t)m * 4096 + k4) = hv;
    } else {
        int t = (blockIdx.x - 8192) * 256 + threadIdx.x;   // 0..65535
        int i23 = t & 63, i2 = i23 >> 3, i3 = i23 & 7;
        int j23 = (t >> 6) & 63, j2 = j23 >> 3, j3 = j23 & 7;
        int a2 = t >> 12;
        float s = 0.f;
#pragma unroll
        for (int a3 = 0; a3 < 16; ++a3)
            s += core2[(a2 * 8 + j2) * 128 + i2 * 16 + a3] *
                 core3[(a3 * 8 + j3) * 8 + i3];
        g_M1[t] = s;
    }
}

// ---------------------------------------------------------------------------
// Fused steps 2+3, 4-wide:
//   m2v[a1] = sum_a2 core1[(a1*8+j1), i1*16+a2] * M1[a2, j23, i23]
//   W[(j0*512+j123), (i0*512+i123)] = sum_a1 core0[j0, i0*16+a1] * m2v[a1]
// Grid 256 blocks x 256 threads. Block b covers j123 in {2b, 2b+1} (same j1).
// Thread: jj = tid>>7 selects j123; tid2 = tid&127; i123 = tid2*4 .. +3.
__global__ void compose_m2w(const float* __restrict__ core0,
                            const float* __restrict__ core1) {
    __shared__ float s_c0[1024];        // core0: 8 x 128
    __shared__ float s_c1[16 * 128];    // core1 rows (a1*8 + j1)
    __shared__ float s_m1[2][16 * 64];  // M1[a2, j23a/b, :]

    const int j123_0 = blockIdx.x * 2;
    const int j1 = j123_0 >> 6;         // shared by the pair
    const int j23_0 = j123_0 & 63;

    for (int idx = threadIdx.x; idx < 1024; idx += 256)
        s_c0[idx] = core0[idx];
    for (int idx = threadIdx.x; idx < 2048; idx += 256) {
        int a1 = idx >> 7, col = idx & 127;
        s_c1[idx] = core1[(a1 * 8 + j1) * 128 + col];
    }
    for (int idx = threadIdx.x; idx < 2048; idx += 256) {
        int half = idx >> 10, rest = idx & 1023;
        int a2 = rest >> 6, ii = rest & 63;
        s_m1[half][rest] = g_M1[(a2 * 64 + j23_0 + half) * 64 + ii];
    }
    __syncthreads();

    const int jj = threadIdx.x >> 7;          // 0/1 -> j123
    const int tid2 = threadIdx.x & 127;
    const int j123 = j123_0 + jj;
    const int i123 = tid2 * 4;                // 4 consecutive i123
    const int i1 = i123 >> 6;                 // same for all 4
    const int i23 = i123 & 63;                // 16B-aligned float4 index

    float m2v[16][4];
#pragma unroll
    for (int a1 = 0; a1 < 16; ++a1) {
        float s0 = 0.f, s1 = 0.f, s2 = 0.f, s3 = 0.f;
#pragma unroll
        for (int a2 = 0; a2 < 16; ++a2) {
            float c1v = s_c1[a1 * 128 + i1 * 16 + a2];
            float4 m = *(const float4*)&s_m1[jj][a2 * 64 + i23];
            s0 += c1v * m.x; s1 += c1v * m.y;
            s2 += c1v * m.z; s3 += c1v * m.w;
        }
        m2v[a1][0] = s0; m2v[a1][1] = s1; m2v[a1][2] = s2; m2v[a1][3] = s3;
    }

#pragma unroll
    for (int j0 = 0; j0 < 8; ++j0) {
#pragma unroll
        for (int i0 = 0; i0 < 8; ++i0) {
            float s0 = 0.f, s1 = 0.f, s2 = 0.f, s3 = 0.f;
#pragma unroll
            for (int a1 = 0; a1 < 16; ++a1) {
                float c0v = s_c0[j0 * 128 + i0 * 16 + a1];
                s0 += c0v * m2v[a1][0]; s1 += c0v * m2v[a1][1];
                s2 += c0v * m2v[a1][2]; s3 += c0v * m2v[a1][3];
            }
            size_t row = (size_t)(j0 * 512 + j123);
            size_t col = (size_t)(i0 * 512 + i123);
            ushort4 hv = make_ushort4(__half_as_ushort(__float2half(s0)),
                                      __half_as_ushort(__float2half(s1)),
                                      __half_as_ushort(__float2half(s2)),
                                      __half_as_ushort(__float2half(s3)));
            *(ushort4*)(g_Bp + row * 4096 + col) = hv;
        }
    }
}

// ---------------------------------------------------------------------------
// HMMA GEMM: C[2048,4096] = A[2048,4096] @ B[4096,4096]^T + bias
// (unchanged — at the HMMA issue floor)
// ---------------------------------------------------------------------------
#define NKT 64                    // 4096 / 64
#define STAGE_BYTES 32768         // A 16KB + B 16KB
#define SM_TOTAL (3 * STAGE_BYTES)

__device__ __forceinline__ uint32_t smem_u32(const void* p) {
    uint32_t a;
    asm("{ .reg .u64 t; cvta.to.shared.u64 t, %1; cvt.u32.u64 %0, t; }"
        : "=r"(a) : "l"(p));
    return a;
}
__device__ __forceinline__ void cp16(uint32_t dst, const void* src) {
    asm volatile("cp.async.cg.shared.global [%0], [%1], 16;"
                 :: "r"(dst), "l"(src));
}
__device__ __forceinline__ void ldsm4(uint32_t (&r)[4], uint32_t addr) {
    asm volatile("ldmatrix.sync.aligned.m8n8.x4.shared.b16 {%0,%1,%2,%3}, [%4];"
                 : "=r"(r[0]), "=r"(r[1]), "=r"(r[2]), "=r"(r[3]) : "r"(addr));
}
__device__ __forceinline__ void mma16816(float (&d)[4], const uint32_t (&a)[4],
                                         uint32_t b0, uint32_t b1) {
    asm volatile(
        "mma.sync.aligned.m16n8k16.row.col.f32.f16.f16.f32 "
        "{%0,%1,%2,%3}, {%4,%5,%6,%7}, {%8,%9}, {%0,%1,%2,%3};"
        : "+f"(d[0]), "+f"(d[1]), "+f"(d[2]), "+f"(d[3])
        : "r"(a[0]), "r"(a[1]), "r"(a[2]), "r"(a[3]), "r"(b0), "r"(b1));
}

__global__ __launch_bounds__(256, 2)
void tt_gemm_mma(const float* __restrict__ bias, float* __restrict__ C) {
    extern __shared__ char smem[];
    const uint32_t sbase = smem_u32(smem);
    const int tid = threadIdx.x;
    const int wid = tid >> 5;
    const int lane = tid & 31;
    const int bm = blockIdx.y * 128;
    const int bn = blockIdx.x * 128;

    const int mw = wid >> 1;     // 0..3 -> m offset 32*mw
    const int nw = wid & 1;      // 0..1 -> n offset 64*nw

    // ---- cp.async producer: 128 rows x 8 chunks(16B) per operand ----
    const int ld_row = tid >> 1;           // 0..127
    const int ld_seg = (tid & 1) * 4;      // chunk 0..3 or 4..7
    const int ld_xor = ld_row & 7;
    const __half* agp = g_Ap + (size_t)(bm + ld_row) * 4096 + ld_seg * 8;
    const __half* bgp = g_Bp + (size_t)(bn + ld_row) * 4096 + ld_seg * 8;
    const uint32_t a_dst_row = sbase + (uint32_t)ld_row * 128;
    const uint32_t b_dst_row = sbase + 16384u + (uint32_t)ld_row * 128;

    auto issue_stage = [&](int kt, int stg) {
        const uint32_t so = (uint32_t)stg * STAGE_BYTES;
        const __half* asrc = agp + kt * 64;
        const __half* bsrc = bgp + kt * 64;
#pragma unroll
        for (int q = 0; q < 4; ++q) {
            uint32_t sw = (uint32_t)(((ld_seg + q) ^ ld_xor) * 16);
            cp16(a_dst_row + so + sw, asrc + q * 8);
            cp16(b_dst_row + so + sw, bsrc + q * 8);
        }
        asm volatile("cp.async.commit_group;" ::: "memory");
    };

    // ---- ldmatrix consumer addresses ----
    const int a_r = mw * 32 + (lane & 15);                          // + mi*16
    const int a_half = lane >> 4;
    const int b_r = nw * 64 + (lane & 7) + ((lane >> 4) & 1) * 8;   // + g*16
    const int b_half = (lane >> 3) & 1;
    const int c_xor = lane & 7;

    float acc[2][8][4];
#pragma unroll
    for (int mi = 0; mi < 2; ++mi)
#pragma unroll
        for (int nf = 0; nf < 8; ++nf)
#pragma unroll
            for (int v = 0; v < 4; ++v) acc[mi][nf][v] = 0.f;

    issue_stage(0, 0);
    issue_stage(1, 1);

    for (int kt = 0; kt < NKT; ++kt) {
        asm volatile("cp.async.wait_group 1;" ::: "memory");
        __syncthreads();
        if (kt + 2 < NKT) issue_stage(kt + 2, (kt + 2) % 3);

        const uint32_t so = (uint32_t)(kt % 3) * STAGE_BYTES;
        const uint32_t abase = sbase + so;
        const uint32_t bbase = sbase + so + 16384u;

#pragma unroll
        for (int s = 0; s < 4; ++s) {
            uint32_t a[2][4];
#pragma unroll
            for (int mi = 0; mi < 2; ++mi) {
                uint32_t ch = (uint32_t)((s * 2 + a_half) ^ c_xor);
                ldsm4(a[mi], abase + (uint32_t)(a_r + mi * 16) * 128 + ch * 16);
            }
            uint32_t b[4][4];
#pragma unroll
            for (int g = 0; g < 4; ++g) {
                uint32_t ch = (uint32_t)((s * 2 + b_half) ^ c_xor);
                ldsm4(b[g], bbase + (uint32_t)(b_r + g * 16) * 128 + ch * 16);
            }
#pragma unroll
            for (int mi = 0; mi < 2; ++mi)
#pragma unroll
                for (int g = 0; g < 4; ++g) {
                    mma16816(acc[mi][2 * g],     a[mi], b[g][0], b[g][1]);
                    mma16816(acc[mi][2 * g + 1], a[mi], b[g][2], b[g][3]);
                }
        }
    }

    // ---- epilogue: + bias, float2 stores ----
    const int er = lane >> 2;            // 0..7
    const int ec = (lane & 3) * 2;       // 0,2,4,6
#pragma unroll
    for (int mi = 0; mi < 2; ++mi) {
        const int m0 = bm + mw * 32 + mi * 16 + er;
#pragma unroll
        for (int nf = 0; nf < 8; ++nf) {
            const int n0 = bn + nw * 64 + nf * 8 + ec;
            const float2 bv = __ldg((const float2*)(bias + n0));
            float2 o0, o1;
            o0.x = acc[mi][nf][0] + bv.x;
            o0.y = acc[mi][nf][1] + bv.y;
            o1.x = acc[mi][nf][2] + bv.x;
            o1.y = acc[mi][nf][3] + bv.y;
            *(float2*)(C + (size_t)m0 * 4096 + n0) = o0;
            *(float2*)(C + (size_t)(m0 + 8) * 4096 + n0) = o1;
        }
    }
}

// ---------------------------------------------------------------------------
extern "C" void kernel_launch(void* const* d_in, const int* in_sizes, int n_in,
                              void* d_out, int out_size) {
    const float* x = (const float*)d_in[0];
    const float* core0 = (const float*)d_in[1];
    const float* core1 = (const float*)d_in[2];
    const float* core2 = (const float*)d_in[3];
    const float* core3 = (const float*)d_in[4];
    const float* bias = (const float*)d_in[5];
    float* out = (float*)d_out;

    cudaFuncSetAttribute(tt_gemm_mma, cudaFuncAttributeMaxDynamicSharedMemorySize, SM_TOTAL);

    convert_and_m1<<<8448, 256>>>(x, core2, core3);
    compose_m2w<<<256, 256>>>(core0, core1);
    dim3 grid(4096 / 128, 2048 / 128);   // 32 x 16 = 512 CTAs
    tt_gemm_mma<<<grid, 256, SM_TOTAL>>>(bias, out);
}